// round 8
// baseline (speedup 1.0000x reference)
#include <cuda_runtime.h>
#include <cstdint>

#define BATCH 32
#define NP    576
#define NTXT  77
#define NTOK  654
#define EMB   768
#define HD    384
#define SRS   656          // scores row stride (41*16)
#define INV_SQRT_E 0.03608439182435161f

#define AKP   12           // smem row stride in u32 (48B)
#define A_PL  6144         // bytes per A plane per stage (128*48)
#define B_PL  3072         // bytes per B plane per stage (64*48)
#define STG_B 18432        // stage bytes: 2*A_PL + 2*B_PL
#define NSTG  4
#define DSMB  (NSTG * STG_B)

// ---------------- fp32 scratch ----------------
__device__ float g_t[(size_t)BATCH * NTOK * EMB];
__device__ float g_f[(size_t)BATCH * NTOK * EMB];
__device__ float g_v[(size_t)BATCH * NTOK * EMB];
__device__ float g_s[(size_t)BATCH * 2 * NTOK * SRS];
__device__ float g_m[BATCH * EMB];
__device__ float g_bqkv[2304];

// ---------------- split bf16 buffers ----------------
#define PAW ((size_t)18432 * 768)
#define HQW ((size_t)20928 * 768)
#define SXW ((size_t)64 * NTOK * SRS)
#define VTW ((size_t)BATCH * EMB * SRS)
__device__ uint16_t g_pa_h[PAW], g_pa_l[PAW];
__device__ uint16_t g_h_h[HQW],  g_h_l[HQW];
__device__ uint16_t g_q_h[HQW],  g_q_l[HQW];
__device__ uint16_t g_k_h[HQW],  g_k_l[HQW];
__device__ uint16_t g_o_h[HQW],  g_o_l[HQW];
__device__ uint16_t g_sx_h[SXW], g_sx_l[SXW];
__device__ uint16_t g_vt_h[VTW], g_vt_l[VTW];
__device__ uint16_t g_m_h[32*768], g_m_l[32*768];
__device__ uint16_t g_wh[6][768*768], g_wl[6][768*768];  // transposed [N][K]; slots 1..3 form QKV [2304][768]

// ---------------- helpers ----------------
__device__ __forceinline__ float warpSum(float v) {
#pragma unroll
    for (int o = 16; o; o >>= 1) v += __shfl_xor_sync(0xffffffffu, v, o);
    return v;
}
__device__ __forceinline__ float warpMax(float v) {
#pragma unroll
    for (int o = 16; o; o >>= 1) v = fmaxf(v, __shfl_xor_sync(0xffffffffu, v, o));
    return v;
}
__device__ __forceinline__ void bsplit1(float x, uint16_t& h, uint16_t& l) {
    uint32_t u = __float_as_uint(x);
    uint32_t hu = (u + 0x8000u) & 0xffff0000u;
    float lo = x - __uint_as_float(hu);
    h = (uint16_t)(hu >> 16);
    l = (uint16_t)((__float_as_uint(lo) + 0x8000u) >> 16);
}
__device__ __forceinline__ void cpa(uint32_t dst, const void* src) {
    asm volatile("cp.async.cg.shared.global [%0], [%1], 16;" :: "r"(dst), "l"(src));
}
#define CPCOMMIT asm volatile("cp.async.commit_group;")
#define CPWAIT(n) asm volatile("cp.async.wait_group %0;" :: "n"(n))

__device__ __forceinline__ void mma16(float c[4], uint32_t a0, uint32_t a1,
                                      uint32_t a2, uint32_t a3,
                                      uint32_t b0, uint32_t b1) {
    asm volatile(
        "mma.sync.aligned.m16n8k16.row.col.f32.bf16.bf16.f32 "
        "{%0,%1,%2,%3},{%4,%5,%6,%7},{%8,%9},{%0,%1,%2,%3};"
        : "+f"(c[0]), "+f"(c[1]), "+f"(c[2]), "+f"(c[3])
        : "r"(a0), "r"(a1), "r"(a2), "r"(a3), "r"(b0), "r"(b1));
}

// one 128x64x16 chunk, 3-term bf16 compensated (round-5 proven)
__device__ __forceinline__ void mma_chunk(const uint32_t* __restrict__ Ah,
                                          const uint32_t* __restrict__ Al,
                                          const uint32_t* __restrict__ Bh,
                                          const uint32_t* __restrict__ Bl,
                                          int wm, int wn, int lane,
                                          float acc[2][4][4]) {
    int g = lane >> 2, t = lane & 3;
    uint32_t bh[4][2], bl[4][2];
#pragma unroll
    for (int ni = 0; ni < 4; ni++) {
        int c = wn * 32 + ni * 8 + g;
        bh[ni][0] = Bh[c * AKP + t];
        bh[ni][1] = Bh[c * AKP + t + 4];
        bl[ni][0] = Bl[c * AKP + t];
        bl[ni][1] = Bl[c * AKP + t + 4];
    }
#pragma unroll
    for (int mi = 0; mi < 2; mi++) {
        int r = wm * 32 + mi * 16 + g;
        uint32_t ah0 = Ah[r * AKP + t],     ah1 = Ah[(r + 8) * AKP + t];
        uint32_t ah2 = Ah[r * AKP + t + 4], ah3 = Ah[(r + 8) * AKP + t + 4];
        uint32_t al0 = Al[r * AKP + t],     al1 = Al[(r + 8) * AKP + t];
        uint32_t al2 = Al[r * AKP + t + 4], al3 = Al[(r + 8) * AKP + t + 4];
#pragma unroll
        for (int ni = 0; ni < 4; ni++) {
            mma16(acc[mi][ni], ah0, ah1, ah2, ah3, bh[ni][0], bh[ni][1]);
            mma16(acc[mi][ni], ah0, ah1, ah2, ah3, bl[ni][0], bl[ni][1]);
            mma16(acc[mi][ni], al0, al1, al2, al3, bh[ni][0], bh[ni][1]);
        }
    }
}

// load one k16 chunk (A 128 rows hi/lo + B 64 rows hi/lo) into one stage
__device__ __forceinline__ void load_chunk(
    const uint16_t* __restrict__ aH, const uint16_t* __restrict__ aL,
    size_t lda, int armax, int row0,
    const uint16_t* __restrict__ bH, const uint16_t* __restrict__ bL,
    size_t ldb, int brmax, int col0,
    int kt, uint32_t sbase, int tid) {
    int am = tid >> 1, aj = tid & 1;
    int gr = row0 + am; if (gr > armax) gr = armax;
    size_t aoff = (size_t)gr * lda + (size_t)kt * 16 + aj * 8;
    uint32_t adst = sbase + (uint32_t)(am * 48 + aj * 16);
    cpa(adst, aH + aoff);
    cpa(adst + A_PL, aL + aoff);
    int brem = tid & 127, barr = tid >> 7;
    int bc = col0 + (brem >> 1); if (bc > brmax) bc = brmax;
    int bj = brem & 1;
    size_t boff = (size_t)bc * ldb + (size_t)kt * 16 + bj * 8;
    uint32_t bdst = sbase + 2u * A_PL + (uint32_t)(barr * B_PL + (brem >> 1) * 48 + bj * 16);
    cpa(bdst, (barr ? bL : bH) + boff);
    CPCOMMIT;
}

// 4-stage pipeline, one __syncthreads per chunk, constant group-count discipline
__device__ __forceinline__ void mm_loop(
    const uint16_t* __restrict__ aH, const uint16_t* __restrict__ aL,
    size_t lda, int armax, int row0,
    const uint16_t* __restrict__ bH, const uint16_t* __restrict__ bL,
    size_t ldb, int brmax, int col0,
    int KT, char* dsm, uint32_t smu, int wm, int wn, int lane,
    float acc[2][4][4]) {
    int tid = threadIdx.x;
#pragma unroll
    for (int i = 0; i < 3; i++) {
        if (i < KT)
            load_chunk(aH, aL, lda, armax, row0, bH, bL, ldb, brmax, col0,
                       i, smu + (uint32_t)i * STG_B, tid);
        else
            CPCOMMIT;
    }
    for (int kt = 0; kt < KT; kt++) {
        CPWAIT(2);
        __syncthreads();
        if (kt + 3 < KT)
            load_chunk(aH, aL, lda, armax, row0, bH, bL, ldb, brmax, col0,
                       kt + 3, smu + (uint32_t)((kt + 3) & 3) * STG_B, tid);
        else
            CPCOMMIT;
        char* stg = dsm + (size_t)(kt & 3) * STG_B;
        mma_chunk((const uint32_t*)stg,
                  (const uint32_t*)(stg + A_PL),
                  (const uint32_t*)(stg + 2 * A_PL),
                  (const uint32_t*)(stg + 2 * A_PL + B_PL),
                  wm, wn, lane, acc);
    }
    __syncthreads();
}

#define MM_PROLOG()                                                      \
    extern __shared__ char dsm[];                                        \
    uint32_t smu = (uint32_t)__cvta_generic_to_shared(dsm);              \
    int tid = threadIdx.x, lane = tid & 31, wid = tid >> 5;              \
    int wm = wid & 3, wn = wid >> 2;                                     \
    float acc[2][4][4] = {};                                             \
    (void)tid;

// ---------------- generic GEMM: modes 0=fp32, 1=fp32+patch remap, 2=qkv ------
__global__ void __launch_bounds__(256, 2)
gemm_k(const uint16_t* __restrict__ Ah, const uint16_t* __restrict__ Al, int lda,
       const uint16_t* __restrict__ Bh, const uint16_t* __restrict__ Bl,
       int brmax,
       const float* __restrict__ bias,
       float* __restrict__ Cf, int ldc, int M, int KT, int mode) {
    MM_PROLOG();
    int row0 = blockIdx.y * 128, col0 = blockIdx.x * 64;
    mm_loop(Ah, Al, lda, M - 1, row0, Bh, Bl, lda, brmax, col0,
            KT, dsm, smu, wm, wn, lane, acc);
    int g = lane >> 2, t = lane & 3;
#pragma unroll
    for (int mi = 0; mi < 2; mi++)
#pragma unroll
        for (int e = 0; e < 2; e++) {
            int r = row0 + wm * 32 + mi * 16 + g + e * 8;
            if (r >= M) continue;
#pragma unroll
            for (int ni = 0; ni < 4; ni++) {
                int c = col0 + wn * 32 + ni * 8 + t * 2;
                float v0 = acc[mi][ni][e * 2 + 0];
                float v1 = acc[mi][ni][e * 2 + 1];
                if (mode == 2) {
                    v0 += g_bqkv[c]; v1 += g_bqkv[c + 1];
                    int seg = (c >= 1536) ? 2 : (c >= 768 ? 1 : 0);
                    size_t idx = (size_t)r * 768 + (c - seg * 768);
                    if (seg == 0) {
                        uint16_t h0, l0, h1, l1;
                        bsplit1(v0, h0, l0); bsplit1(v1, h1, l1);
                        g_q_h[idx] = h0; g_q_h[idx + 1] = h1;
                        g_q_l[idx] = l0; g_q_l[idx + 1] = l1;
                    } else if (seg == 1) {
                        uint16_t h0, l0, h1, l1;
                        bsplit1(v0, h0, l0); bsplit1(v1, h1, l1);
                        g_k_h[idx] = h0; g_k_h[idx + 1] = h1;
                        g_k_l[idx] = l0; g_k_l[idx + 1] = l1;
                    } else {
                        g_v[idx] = v0; g_v[idx + 1] = v1;
                    }
                } else {
                    if (bias) { v0 += bias[c]; v1 += bias[c + 1]; }
                    size_t orow = (mode == 1)
                        ? ((size_t)r + (size_t)(r / NP) * 78 + 1) : (size_t)r;
                    size_t idx = orow * ldc + c;
                    Cf[idx] = v0; Cf[idx + 1] = v1;
                }
            }
        }
}

// ---------------- scores = q @ k^T per (b,h) ---------------------------------
__global__ void __launch_bounds__(256, 2) scores_k() {
    MM_PROLOG();
    const int z = blockIdx.z, b = z >> 1, hh = z & 1;
    int row0 = blockIdx.y * 128, col0 = blockIdx.x * 64;
    size_t base = (size_t)(b * NTOK) * EMB + (size_t)hh * HD;
    mm_loop(g_q_h + base, g_q_l + base, EMB, NTOK - 1, row0,
            g_k_h + base, g_k_l + base, EMB, NTOK - 1, col0,
            HD / 16, dsm, smu, wm, wn, lane, acc);
    float* C = g_s + (size_t)z * NTOK * SRS;
    int g = lane >> 2, t = lane & 3;
#pragma unroll
    for (int mi = 0; mi < 2; mi++)
#pragma unroll
        for (int e = 0; e < 2; e++) {
            int r = row0 + wm * 32 + mi * 16 + g + e * 8;
            if (r >= NTOK) continue;
#pragma unroll
            for (int ni = 0; ni < 4; ni++) {
                int c = col0 + wn * 32 + ni * 8 + t * 2;
                if (c < NTOK)     C[(size_t)r * SRS + c]     = acc[mi][ni][e * 2 + 0];
                if (c + 1 < NTOK) C[(size_t)r * SRS + c + 1] = acc[mi][ni][e * 2 + 1];
            }
        }
}

// ---------------- o = attn @ v per (b,h) --------------------------------------
__global__ void __launch_bounds__(256, 2) av_k() {
    MM_PROLOG();
    const int z = blockIdx.z, b = z >> 1, hh = z & 1;
    int row0 = blockIdx.y * 128, col0 = blockIdx.x * 64;
    size_t abase = (size_t)z * NTOK * SRS;
    size_t bbase = ((size_t)b * EMB + (size_t)hh * HD) * SRS;
    mm_loop(g_sx_h + abase, g_sx_l + abase, SRS, NTOK - 1, row0,
            g_vt_h + bbase, g_vt_l + bbase, SRS, HD - 1, col0,
            SRS / 16, dsm, smu, wm, wn, lane, acc);
    int g = lane >> 2, t = lane & 3;
#pragma unroll
    for (int mi = 0; mi < 2; mi++)
#pragma unroll
        for (int e = 0; e < 2; e++) {
            int r = row0 + wm * 32 + mi * 16 + g + e * 8;
            if (r >= NTOK) continue;
#pragma unroll
            for (int ni = 0; ni < 4; ni++) {
                int c = col0 + wn * 32 + ni * 8 + t * 2;
                size_t idx = ((size_t)(b * NTOK) + r) * EMB + hh * HD + c;
                uint16_t h0, l0, h1, l1;
                bsplit1(acc[mi][ni][e * 2 + 0], h0, l0);
                bsplit1(acc[mi][ni][e * 2 + 1], h1, l1);
                g_o_h[idx] = h0; g_o_h[idx + 1] = h1;
                g_o_l[idx] = l0; g_o_l[idx + 1] = l1;
            }
        }
}

// ---------------- softmax row / sqrt(768) -> split bf16, zero pads -------------
__global__ void softmax_kernel() {
    size_t row = blockIdx.x;
    const float* r = g_s + row * SRS;
    uint16_t* oh = g_sx_h + row * SRS;
    uint16_t* ol = g_sx_l + row * SRS;
    int tid = threadIdx.x;
    __shared__ float sh[8];
    __shared__ float shb;

    float mx = -1e30f;
    for (int i = tid; i < NTOK; i += 256) mx = fmaxf(mx, r[i]);
    mx = warpMax(mx);
    if ((tid & 31) == 0) sh[tid >> 5] = mx;
    __syncthreads();
    if (tid == 0) {
        float m = sh[0];
#pragma unroll
        for (int i = 1; i < 8; i++) m = fmaxf(m, sh[i]);
        shb = m;
    }
    __syncthreads();
    mx = shb;

    float sum = 0.f;
    float ev[3];
    int cnt = 0;
    for (int i = tid; i < NTOK; i += 256) { ev[cnt] = __expf(r[i] - mx); sum += ev[cnt]; cnt++; }
    sum = warpSum(sum);
    if ((tid & 31) == 0) sh[tid >> 5] = sum;
    __syncthreads();
    if (tid == 0) {
        float s = 0.f;
#pragma unroll
        for (int i = 0; i < 8; i++) s += sh[i];
        shb = s;
    }
    __syncthreads();
    float inv = INV_SQRT_E / shb;
    cnt = 0;
    for (int i = tid; i < NTOK; i += 256) {
        uint16_t h, l;
        bsplit1(ev[cnt++] * inv, h, l);
        oh[i] = h; ol[i] = l;
    }
    if (tid < SRS - NTOK) { oh[NTOK + tid] = 0; ol[NTOK + tid] = 0; }
}

// ---------------- weight transpose + split ------------------------------------
__global__ void wsplit_kernel(const float* __restrict__ W,
                              uint16_t* __restrict__ oh, uint16_t* __restrict__ ol) {
    __shared__ float tile[32][33];
    int tx = threadIdx.x, ty = threadIdx.y;
    int k0 = blockIdx.x * 32, n0 = blockIdx.y * 32;
#pragma unroll
    for (int i = 0; i < 32; i += 8)
        tile[ty + i][tx] = W[(size_t)(k0 + ty + i) * 768 + n0 + tx];
    __syncthreads();
#pragma unroll
    for (int i = 0; i < 32; i += 8) {
        uint16_t h, l;
        bsplit1(tile[tx][ty + i], h, l);
        size_t idx = (size_t)(n0 + ty + i) * 768 + k0 + tx;
        oh[idx] = h; ol[idx] = l;
    }
}

__global__ void concat_bias(const float* __restrict__ bq, const float* __restrict__ bk,
                            const float* __restrict__ bv) {
    int i = blockIdx.x * 256 + threadIdx.x;
    if (i < 768) g_bqkv[i] = bq[i];
    else if (i < 1536) g_bqkv[i] = bk[i - 768];
    else if (i < 2304) g_bqkv[i] = bv[i - 1536];
}

// ---------------- v transpose + split to [b][emb][SRS] --------------------------
__global__ void vtrans_kernel() {
    __shared__ float tile[32][33];
    int tx = threadIdx.x, ty = threadIdx.y;
    int b = blockIdx.z;
    int t0 = blockIdx.x * 32, e0 = blockIdx.y * 32;
    const float* v = g_v + (size_t)b * NTOK * EMB;
#pragma unroll
    for (int i = 0; i < 32; i += 8) {
        int tok = t0 + ty + i;
        tile[ty + i][tx] = (tok < NTOK) ? v[(size_t)tok * EMB + e0 + tx] : 0.f;
    }
    __syncthreads();
#pragma unroll
    for (int i = 0; i < 32; i += 8) {
        int tok = t0 + tx, e = e0 + ty + i;
        if (tok < SRS) {
            uint16_t h, l;
            bsplit1(tile[tx][ty + i], h, l);
            size_t idx = ((size_t)b * EMB + e) * SRS + tok;
            g_vt_h[idx] = h; g_vt_l[idx] = l;
        }
    }
}

// ---------------- patch gather + split ------------------------------------------
__global__ void patch_extract_split(const float* __restrict__ x) {
    long idx = (long)blockIdx.x * blockDim.x + threadIdx.x;
    const long total = (long)BATCH * 3 * 384 * 384;
    if (idx >= total) return;
    int ww = (int)(idx % 384);
    long t1 = idx / 384;
    int hh = (int)(t1 % 384);
    long t2 = t1 / 384;
    int c = (int)(t2 % 3);
    int b = (int)(t2 / 3);
    int j = (hh >> 4) * 24 + (ww >> 4);
    int k = (hh & 15) * 48 + (ww & 15) * 3 + c;
    size_t o = ((size_t)(b * NP + j)) * EMB + k;
    uint16_t h, l;
    bsplit1(x[idx], h, l);
    g_pa_h[o] = h; g_pa_l[o] = l;
}

__global__ void fill_cls_text(const float* __restrict__ cls, const float* __restrict__ txt) {
    long idx = (long)blockIdx.x * blockDim.x + threadIdx.x;
    const long total = (long)BATCH * (1 + NTXT) * EMB;
    if (idx >= total) return;
    int e = (int)(idx % EMB);
    long r = idx / EMB;
    int tok = (int)(r % (1 + NTXT));
    int b = (int)(r / (1 + NTXT));
    if (tok == 0)
        g_t[((size_t)b * NTOK) * EMB + e] = cls[e];
    else
        g_t[((size_t)b * NTOK + NP + tok) * EMB + e] = txt[((size_t)b * NTXT + (tok - 1)) * EMB + e];
}

// ---------------- LayerNorm 768 --------------------------------------------------
__device__ __forceinline__ void ln_stats(const float* r, int tid, float v[3],
                                         float& mean, float& rstd) {
    v[0] = r[tid]; v[1] = r[tid + 256]; v[2] = r[tid + 512];
    float s = v[0] + v[1] + v[2];
    float ss = v[0] * v[0] + v[1] * v[1] + v[2] * v[2];
    s = warpSum(s); ss = warpSum(ss);
    __shared__ float sh1[8], sh2[8];
    __shared__ float smean, srstd;
    if ((tid & 31) == 0) { sh1[tid >> 5] = s; sh2[tid >> 5] = ss; }
    __syncthreads();
    if (tid == 0) {
        float a = 0.f, b2 = 0.f;
#pragma unroll
        for (int i = 0; i < 8; i++) { a += sh1[i]; b2 += sh2[i]; }
        float m = a * (1.f / 768.f);
        smean = m;
        srstd = rsqrtf(b2 * (1.f / 768.f) - m * m + 1e-5f);
    }
    __syncthreads();
    mean = smean; rstd = srstd;
}

__global__ void ln768_split(const float* __restrict__ in,
                            const float* __restrict__ g, const float* __restrict__ be,
                            uint16_t* __restrict__ oh, uint16_t* __restrict__ ol) {
    size_t row = blockIdx.x;
    int tid = threadIdx.x;
    float v[3], mean, rstd;
    ln_stats(in + row * EMB, tid, v, mean, rstd);
#pragma unroll
    for (int i = 0; i < 3; i++) {
        int c = tid + i * 256;
        float val = (v[i] - mean) * rstd * g[c] + be[c];
        uint16_t h, l;
        bsplit1(val, h, l);
        oh[row * EMB + c] = h; ol[row * EMB + c] = l;
    }
}

__global__ void ln768_add(const float* __restrict__ in,
                          const float* __restrict__ g, const float* __restrict__ be,
                          float* __restrict__ out) {
    size_t row = blockIdx.x;
    int tid = threadIdx.x;
    float v[3], mean, rstd;
    ln_stats(in + row * EMB, tid, v, mean, rstd);
#pragma unroll
    for (int i = 0; i < 3; i++) {
        int c = tid + i * 256;
        out[row * EMB + c] += (v[i] - mean) * rstd * g[c] + be[c];
    }
}

__global__ void meanpool_kernel() {
    int b = blockIdx.x;
    int e = threadIdx.x;
    const float* base = g_t + (size_t)b * NTOK * EMB + e;
    float s = 0.f;
    for (int i = 0; i < NTOK; i++) s += base[(size_t)i * EMB];
    g_m[b * EMB + e] = s * (1.f / (float)NTOK);
}

// ---------------- launch -----------------------------------------------------------
extern "C" void kernel_launch(void* const* d_in, const int* in_sizes, int n_in,
                              void* d_out, int out_size) {
    const float* x    = (const float*)d_in[0];
    const float* txt  = (const float*)d_in[1];
    const float* Wpa  = (const float*)d_in[2];
    const float* bpa  = (const float*)d_in[3];
    const float* cls  = (const float*)d_in[4];
    const float* g1   = (const float*)d_in[5];
    const float* be1  = (const float*)d_in[6];
    const float* Wq   = (const float*)d_in[7];
    const float* bq   = (const float*)d_in[8];
    const float* Wk   = (const float*)d_in[9];
    const float* bk   = (const float*)d_in[10];
    const float* Wv   = (const float*)d_in[11];
    const float* bv   = (const float*)d_in[12];
    const float* Wp   = (const float*)d_in[13];
    const float* bp   = (const float*)d_in[14];
    const float* g2   = (const float*)d_in[15];
    const float* be2  = (const float*)d_in[16];
    const float* g3   = (const float*)d_in[17];
    const float* be3  = (const float*)d_in[18];
    const float* Wf   = (const float*)d_in[19];
    const float* bf   = (const float*)d_in[20];
    float* out = (float*)d_out;

    cudaFuncSetAttribute(gemm_k,   cudaFuncAttributeMaxDynamicSharedMemorySize, DSMB);
    cudaFuncSetAttribute(scores_k, cudaFuncAttributeMaxDynamicSharedMemorySize, DSMB);
    cudaFuncSetAttribute(av_k,     cudaFuncAttributeMaxDynamicSharedMemorySize, DSMB);

    float *t, *f, *m;
    uint16_t *wh, *wl, *pah, *pal, *hh, *hl, *oh, *ol, *mh, *ml;
    cudaGetSymbolAddress((void**)&t, g_t);
    cudaGetSymbolAddress((void**)&f, g_f);
    cudaGetSymbolAddress((void**)&m, g_m);
    cudaGetSymbolAddress((void**)&wh, g_wh);
    cudaGetSymbolAddress((void**)&wl, g_wl);
    cudaGetSymbolAddress((void**)&pah, g_pa_h);
    cudaGetSymbolAddress((void**)&pal, g_pa_l);
    cudaGetSymbolAddress((void**)&hh, g_h_h);
    cudaGetSymbolAddress((void**)&hl, g_h_l);
    cudaGetSymbolAddress((void**)&oh, g_o_h);
    cudaGetSymbolAddress((void**)&ol, g_o_l);
    cudaGetSymbolAddress((void**)&mh, g_m_h);
    cudaGetSymbolAddress((void**)&ml, g_m_l);

    const int MQKV = BATCH * NTOK;    // 20928
    const int MPATCH = BATCH * NP;    // 18432
    const size_t WSZ = 768 * 768;
    dim3 tb(32, 8), wgrid(24, 24);

    // weight transpose+split (0=Wpa 1=Wq 2=Wk 3=Wv 4=Wp 5=Wf); slots 1..3 contiguous = QKV [2304][768]
    wsplit_kernel<<<wgrid, tb>>>(Wpa, wh + 0 * WSZ, wl + 0 * WSZ);
    wsplit_kernel<<<wgrid, tb>>>(Wq,  wh + 1 * WSZ, wl + 1 * WSZ);
    wsplit_kernel<<<wgrid, tb>>>(Wk,  wh + 2 * WSZ, wl + 2 * WSZ);
    wsplit_kernel<<<wgrid, tb>>>(Wv,  wh + 3 * WSZ, wl + 3 * WSZ);
    wsplit_kernel<<<wgrid, tb>>>(Wp,  wh + 4 * WSZ, wl + 4 * WSZ);
    wsplit_kernel<<<wgrid, tb>>>(Wf,  wh + 5 * WSZ, wl + 5 * WSZ);
    concat_bias<<<9, 256>>>(bq, bk, bv);

    // patches (direct split) + cls/text
    patch_extract_split<<<55296, 256>>>(x);
    fill_cls_text<<<7488, 256>>>(cls, txt);

    // patch GEMM -> t fp32 (remapped rows)
    gemm_k<<<dim3(12, 144), 256, DSMB>>>(pah, pal, EMB, wh + 0 * WSZ, wl + 0 * WSZ,
                                         767, bpa, t, EMB, MPATCH, 48, 1);

    // LN1 -> h split
    ln768_split<<<MQKV, 256>>>(t, g1, be1, hh, hl);

    // fused QKV: N=2304 (q split, k split, v fp32)
    gemm_k<<<dim3(36, 164), 256, DSMB>>>(hh, hl, EMB, wh + 1 * WSZ, wl + 1 * WSZ,
                                         2303, nullptr, nullptr, EMB, MQKV, 48, 2);

    // v transpose+split (pad k to SRS)
    vtrans_kernel<<<dim3(21, 24, BATCH), tb>>>();

    // attention
    scores_k<<<dim3(11, 6, 64), 256, DSMB>>>();
    softmax_kernel<<<64 * NTOK, 256>>>();
    av_k<<<dim3(6, 6, 64), 256, DSMB>>>();

    // proj -> f fp32, then t += LN2(f)
    gemm_k<<<dim3(12, 164), 256, DSMB>>>(oh, ol, EMB, wh + 4 * WSZ, wl + 4 * WSZ,
                                         767, bp, f, EMB, MQKV, 48, 0);
    ln768_add<<<MQKV, 256>>>(f, g2, be2, t);

    // pool, LN3 -> split, final GEMM -> out
    meanpool_kernel<<<BATCH, 768>>>();
    ln768_split<<<BATCH, 256>>>(m, g3, be3, mh, ml);
    gemm_k<<<dim3(12, 1), 256, DSMB>>>(mh, ml, EMB, wh + 5 * WSZ, wl + 5 * WSZ,
                                       767, bf, out, EMB, 32, 48, 0);
}

// round 9
// speedup vs baseline: 1.4052x; 1.4052x over previous
#include <cuda_runtime.h>
#include <cstdint>
#include <cuda_fp16.h>

#define BATCH 32
#define NP    576
#define NTXT  77
#define NTOK  654
#define EMB   768
#define HD    384
#define SRS   656          // scores row stride (41*16)
#define INV_SQRT_E 0.03608439182435161f
#define WSCALE 64.0f
#define IWSCALE 0.015625f

#define AKP   12           // smem row stride in u32 (48B)
#define A_PL  6144         // A hi plane bytes per stage (128*48)
#define B_PL  3072         // B plane bytes per stage (64*48)
#define STG_U 3072         // stage size in u32 (12288B)

// ---------------- fp32 scratch ----------------
__device__ float g_t[(size_t)BATCH * NTOK * EMB];
__device__ float g_f[(size_t)BATCH * NTOK * EMB];
__device__ float g_v[(size_t)BATCH * NTOK * EMB];
__device__ float g_s[(size_t)BATCH * 2 * NTOK * SRS];
__device__ float g_m[BATCH * EMB];

// ---------------- fp16 buffers ----------------
#define PAW ((size_t)18432 * 768)
#define HQW ((size_t)20928 * 768)
#define SXW ((size_t)64 * NTOK * SRS)
#define VTW ((size_t)BATCH * EMB * SRS)
__device__ uint16_t g_pa_h[PAW];                 // patches hi only (A side)
__device__ uint16_t g_h_h[HQW];                  // LN1 out hi only
__device__ uint16_t g_q_h[HQW];                  // q hi only
__device__ uint16_t g_k_h[HQW], g_k_l[HQW];      // k hi+lo (B side)
__device__ uint16_t g_o_h[HQW];                  // attn out hi only
__device__ uint16_t g_sx_h[SXW];                 // softmax hi only
__device__ uint16_t g_vt_h[VTW], g_vt_l[VTW];    // v^T hi+lo (B side)
__device__ uint16_t g_m_h[32*768];               // pooled hi only
__device__ uint16_t g_wh[6][768*768], g_wl[6][768*768];  // weights transposed [N][K], x64

// ---------------- helpers ----------------
__device__ __forceinline__ float warpSum(float v) {
#pragma unroll
    for (int o = 16; o; o >>= 1) v += __shfl_xor_sync(0xffffffffu, v, o);
    return v;
}
__device__ __forceinline__ float warpMax(float v) {
#pragma unroll
    for (int o = 16; o; o >>= 1) v = fmaxf(v, __shfl_xor_sync(0xffffffffu, v, o));
    return v;
}
// fp16 split: hi = h(x), lo = h(x - hi)
__device__ __forceinline__ void hsplit1(float x, uint16_t& h, uint16_t& l) {
    __half hh = __float2half_rn(x);
    float hf = __half2float(hh);
    __half ll = __float2half_rn(x - hf);
    h = __half_as_ushort(hh);
    l = __half_as_ushort(ll);
}
__device__ __forceinline__ uint16_t h16(float x) {
    return __half_as_ushort(__float2half_rn(x));
}
__device__ __forceinline__ void cpa(uint32_t dst, const void* src) {
    asm volatile("cp.async.cg.shared.global [%0], [%1], 16;" :: "r"(dst), "l"(src));
}
#define CPCOMMIT asm volatile("cp.async.commit_group;")
#define CPWAIT(n) asm volatile("cp.async.wait_group %0;" :: "n"(n))

__device__ __forceinline__ void mma16(float c[4], uint32_t a0, uint32_t a1,
                                      uint32_t a2, uint32_t a3,
                                      uint32_t b0, uint32_t b1) {
    asm volatile(
        "mma.sync.aligned.m16n8k16.row.col.f32.f16.f16.f32 "
        "{%0,%1,%2,%3},{%4,%5,%6,%7},{%8,%9},{%0,%1,%2,%3};"
        : "+f"(c[0]), "+f"(c[1]), "+f"(c[2]), "+f"(c[3])
        : "r"(a0), "r"(a1), "r"(a2), "r"(a3), "r"(b0), "r"(b1));
}

// one 128x64x16 chunk, 2-term fp16 (ah*bh + ah*bl)
__device__ __forceinline__ void mma_chunk(const uint32_t* __restrict__ Ah,
                                          const uint32_t* __restrict__ Bh,
                                          const uint32_t* __restrict__ Bl,
                                          int wm, int wn, int lane,
                                          float acc[2][4][4]) {
    int g = lane >> 2, t = lane & 3;
    uint32_t bh[4][2], bl[4][2];
#pragma unroll
    for (int ni = 0; ni < 4; ni++) {
        int c = wn * 32 + ni * 8 + g;
        bh[ni][0] = Bh[c * AKP + t];
        bh[ni][1] = Bh[c * AKP + t + 4];
        bl[ni][0] = Bl[c * AKP + t];
        bl[ni][1] = Bl[c * AKP + t + 4];
    }
#pragma unroll
    for (int mi = 0; mi < 2; mi++) {
        int r = wm * 32 + mi * 16 + g;
        uint32_t a0 = Ah[r * AKP + t],     a1 = Ah[(r + 8) * AKP + t];
        uint32_t a2 = Ah[r * AKP + t + 4], a3 = Ah[(r + 8) * AKP + t + 4];
#pragma unroll
        for (int ni = 0; ni < 4; ni++) {
            mma16(acc[mi][ni], a0, a1, a2, a3, bh[ni][0], bh[ni][1]);
            mma16(acc[mi][ni], a0, a1, a2, a3, bl[ni][0], bl[ni][1]);
        }
    }
}

// load one k16 chunk: A hi (128 rows) + B hi/lo (64 rows) -> one stage
__device__ __forceinline__ void load_chunk(
    const uint16_t* __restrict__ aH, size_t lda, int armax, int row0,
    const uint16_t* __restrict__ bH, const uint16_t* __restrict__ bL,
    size_t ldb, int brmax, int col0,
    int kt, uint32_t sbase, int tid) {
    int am = tid >> 1, aj = tid & 1;
    int gr = row0 + am; if (gr > armax) gr = armax;
    cpa(sbase + (uint32_t)(am * 48 + aj * 16),
        aH + (size_t)gr * lda + (size_t)kt * 16 + aj * 8);
    int brem = tid & 127, plane = tid >> 7;
    int bc = col0 + (brem >> 1); if (bc > brmax) bc = brmax;
    int bj = brem & 1;
    cpa(sbase + (uint32_t)A_PL + (uint32_t)(plane * B_PL + (brem >> 1) * 48 + bj * 16),
        (plane ? bL : bH) + (size_t)bc * ldb + (size_t)kt * 16 + bj * 8);
    CPCOMMIT;
}

// round-5 proven 2-stage loop
#define MM_BODY(aH, lda, armax, row0, bH, bL, ldb, brmax, col0, KT)              \
    load_chunk(aH, lda, armax, row0, bH, bL, ldb, brmax, col0, 0, smu, tid);     \
    for (int kt = 0; kt < (KT); kt++) {                                          \
        int buf = kt & 1;                                                        \
        if (kt + 1 < (KT)) {                                                     \
            load_chunk(aH, lda, armax, row0, bH, bL, ldb, brmax, col0,           \
                       kt + 1, smu + (uint32_t)(buf ^ 1) * (STG_U * 4u), tid);   \
            CPWAIT(1);                                                           \
        } else CPWAIT(0);                                                        \
        __syncthreads();                                                         \
        const uint32_t* stg = &SM[buf][0];                                       \
        mma_chunk(stg, stg + A_PL / 4, stg + (A_PL + B_PL) / 4, wm, wn, lane, acc); \
        __syncthreads();                                                         \
    }

#define MM_PROLOG()                                                      \
    __shared__ uint32_t SM[2][STG_U];                                    \
    uint32_t smu = (uint32_t)__cvta_generic_to_shared(&SM[0][0]);        \
    int tid = threadIdx.x, lane = tid & 31, wid = tid >> 5;              \
    int wm = wid & 3, wn = wid >> 2;                                     \
    float acc[2][4][4] = {};

// ---------------- generic GEMM: C = A[MxK] @ WT[NxK]*IWSCALE + bias ----------
__global__ void __launch_bounds__(256)
gemm_h(const uint16_t* __restrict__ Ah, int lda,
       const uint16_t* __restrict__ Bh, const uint16_t* __restrict__ Bl,
       const float* __restrict__ bias,
       float* __restrict__ Cf, uint16_t* __restrict__ Ch, uint16_t* __restrict__ Cl,
       int ldc, int M, int KT, int remap) {
    MM_PROLOG();
    int row0 = blockIdx.y * 128, col0 = blockIdx.x * 64;
    MM_BODY(Ah, lda, M - 1, row0, Bh, Bl, lda, 767, col0, KT);
    int g = lane >> 2, t = lane & 3;
#pragma unroll
    for (int mi = 0; mi < 2; mi++)
#pragma unroll
        for (int e = 0; e < 2; e++) {
            int r = row0 + wm * 32 + mi * 16 + g + e * 8;
            if (r >= M) continue;
            size_t orow = remap ? ((size_t)r + (size_t)(r / NP) * 78 + 1) : (size_t)r;
#pragma unroll
            for (int ni = 0; ni < 4; ni++) {
                int c = col0 + wn * 32 + ni * 8 + t * 2;
                float v0 = acc[mi][ni][e * 2 + 0] * IWSCALE + bias[c];
                float v1 = acc[mi][ni][e * 2 + 1] * IWSCALE + bias[c + 1];
                size_t idx = orow * ldc + c;
                if (Cf) { Cf[idx] = v0; Cf[idx + 1] = v1; }
                if (Ch) { Ch[idx] = h16(v0); Ch[idx + 1] = h16(v1); }
                if (Cl) {
                    uint16_t h0, l0, h1, l1;
                    hsplit1(v0, h0, l0); hsplit1(v1, h1, l1);
                    Ch[idx] = h0; Ch[idx + 1] = h1;
                    Cl[idx] = l0; Cl[idx + 1] = l1;
                }
            }
        }
}

// ---------------- scores = q @ k^T per (b,h) ---------------------------------
__global__ void __launch_bounds__(256) scores_h() {
    MM_PROLOG();
    const int z = blockIdx.z, b = z >> 1, hh = z & 1;
    int row0 = blockIdx.y * 128, col0 = blockIdx.x * 64;
    size_t base = (size_t)(b * NTOK) * EMB + (size_t)hh * HD;
    MM_BODY(g_q_h + base, EMB, NTOK - 1, row0,
            g_k_h + base, g_k_l + base, EMB, NTOK - 1, col0, HD / 16);
    float* C = g_s + (size_t)z * NTOK * SRS;
    int g = lane >> 2, t = lane & 3;
#pragma unroll
    for (int mi = 0; mi < 2; mi++)
#pragma unroll
        for (int e = 0; e < 2; e++) {
            int r = row0 + wm * 32 + mi * 16 + g + e * 8;
            if (r >= NTOK) continue;
#pragma unroll
            for (int ni = 0; ni < 4; ni++) {
                int c = col0 + wn * 32 + ni * 8 + t * 2;
                if (c < NTOK)     C[(size_t)r * SRS + c]     = acc[mi][ni][e * 2 + 0];
                if (c + 1 < NTOK) C[(size_t)r * SRS + c + 1] = acc[mi][ni][e * 2 + 1];
            }
        }
}

// ---------------- o = attn @ v per (b,h) --------------------------------------
__global__ void __launch_bounds__(256) av_h() {
    MM_PROLOG();
    const int z = blockIdx.z, b = z >> 1, hh = z & 1;
    int row0 = blockIdx.y * 128, col0 = blockIdx.x * 64;
    size_t abase = (size_t)z * NTOK * SRS;
    size_t bbase = ((size_t)b * EMB + (size_t)hh * HD) * SRS;
    MM_BODY(g_sx_h + abase, SRS, NTOK - 1, row0,
            g_vt_h + bbase, g_vt_l + bbase, SRS, HD - 1, col0, SRS / 16);
    int g = lane >> 2, t = lane & 3;
#pragma unroll
    for (int mi = 0; mi < 2; mi++)
#pragma unroll
        for (int e = 0; e < 2; e++) {
            int r = row0 + wm * 32 + mi * 16 + g + e * 8;
            if (r >= NTOK) continue;
#pragma unroll
            for (int ni = 0; ni < 4; ni++) {
                int c = col0 + wn * 32 + ni * 8 + t * 2;
                size_t idx = ((size_t)(b * NTOK) + r) * EMB + hh * HD + c;
                g_o_h[idx]     = h16(acc[mi][ni][e * 2 + 0]);
                g_o_h[idx + 1] = h16(acc[mi][ni][e * 2 + 1]);
            }
        }
}

// ---------------- softmax row / sqrt(768) -> fp16 hi, zero pads ----------------
__global__ void softmax_kernel() {
    size_t row = blockIdx.x;
    const float* r = g_s + row * SRS;
    uint16_t* oh = g_sx_h + row * SRS;
    int tid = threadIdx.x;
    __shared__ float sh[8];
    __shared__ float shb;

    float mx = -1e30f;
    for (int i = tid; i < NTOK; i += 256) mx = fmaxf(mx, r[i]);
    mx = warpMax(mx);
    if ((tid & 31) == 0) sh[tid >> 5] = mx;
    __syncthreads();
    if (tid == 0) {
        float m = sh[0];
#pragma unroll
        for (int i = 1; i < 8; i++) m = fmaxf(m, sh[i]);
        shb = m;
    }
    __syncthreads();
    mx = shb;

    float sum = 0.f;
    float ev[3];
    int cnt = 0;
    for (int i = tid; i < NTOK; i += 256) { ev[cnt] = __expf(r[i] - mx); sum += ev[cnt]; cnt++; }
    sum = warpSum(sum);
    if ((tid & 31) == 0) sh[tid >> 5] = sum;
    __syncthreads();
    if (tid == 0) {
        float s = 0.f;
#pragma unroll
        for (int i = 0; i < 8; i++) s += sh[i];
        shb = s;
    }
    __syncthreads();
    float inv = INV_SQRT_E / shb;
    cnt = 0;
    for (int i = tid; i < NTOK; i += 256) oh[i] = h16(ev[cnt++] * inv);
    if (tid < SRS - NTOK) oh[NTOK + tid] = 0;
}

// ---------------- weight transpose + split (x WSCALE) --------------------------
__global__ void wsplit_kernel(const float* __restrict__ W,
                              uint16_t* __restrict__ oh, uint16_t* __restrict__ ol) {
    __shared__ float tile[32][33];
    int tx = threadIdx.x, ty = threadIdx.y;
    int k0 = blockIdx.x * 32, n0 = blockIdx.y * 32;
#pragma unroll
    for (int i = 0; i < 32; i += 8)
        tile[ty + i][tx] = W[(size_t)(k0 + ty + i) * 768 + n0 + tx];
    __syncthreads();
#pragma unroll
    for (int i = 0; i < 32; i += 8) {
        uint16_t h, l;
        hsplit1(tile[tx][ty + i] * WSCALE, h, l);
        size_t idx = (size_t)(n0 + ty + i) * 768 + k0 + tx;
        oh[idx] = h; ol[idx] = l;
    }
}

// ---------------- v transpose + split to [b][emb][SRS] --------------------------
__global__ void vtrans_kernel() {
    __shared__ float tile[32][33];
    int tx = threadIdx.x, ty = threadIdx.y;
    int b = blockIdx.z;
    int t0 = blockIdx.x * 32, e0 = blockIdx.y * 32;
    const float* v = g_v + (size_t)b * NTOK * EMB;
#pragma unroll
    for (int i = 0; i < 32; i += 8) {
        int tok = t0 + ty + i;
        tile[ty + i][tx] = (tok < NTOK) ? v[(size_t)tok * EMB + e0 + tx] : 0.f;
    }
    __syncthreads();
#pragma unroll
    for (int i = 0; i < 32; i += 8) {
        int tok = t0 + tx, e = e0 + ty + i;
        if (tok < SRS) {
            uint16_t h, l;
            hsplit1(tile[tx][ty + i], h, l);
            size_t idx = ((size_t)b * EMB + e) * SRS + tok;
            g_vt_h[idx] = h; g_vt_l[idx] = l;
        }
    }
}

// ---------------- patch gather + fp16 ------------------------------------------
__global__ void patch_extract_h(const float* __restrict__ x) {
    long idx = (long)blockIdx.x * blockDim.x + threadIdx.x;
    const long total = (long)BATCH * 3 * 384 * 384;
    if (idx >= total) return;
    int ww = (int)(idx % 384);
    long t1 = idx / 384;
    int hh = (int)(t1 % 384);
    long t2 = t1 / 384;
    int c = (int)(t2 % 3);
    int b = (int)(t2 / 3);
    int j = (hh >> 4) * 24 + (ww >> 4);
    int k = (hh & 15) * 48 + (ww & 15) * 3 + c;
    g_pa_h[((size_t)(b * NP + j)) * EMB + k] = h16(x[idx]);
}

__global__ void fill_cls_text(const float* __restrict__ cls, const float* __restrict__ txt) {
    long idx = (long)blockIdx.x * blockDim.x + threadIdx.x;
    const long total = (long)BATCH * (1 + NTXT) * EMB;
    if (idx >= total) return;
    int e = (int)(idx % EMB);
    long r = idx / EMB;
    int tok = (int)(r % (1 + NTXT));
    int b = (int)(r / (1 + NTXT));
    if (tok == 0)
        g_t[((size_t)b * NTOK) * EMB + e] = cls[e];
    else
        g_t[((size_t)b * NTOK + NP + tok) * EMB + e] = txt[((size_t)b * NTXT + (tok - 1)) * EMB + e];
}

// ---------------- LayerNorm 768 --------------------------------------------------
__device__ __forceinline__ void ln_stats(const float* r, int tid, float v[3],
                                         float& mean, float& rstd) {
    v[0] = r[tid]; v[1] = r[tid + 256]; v[2] = r[tid + 512];
    float s = v[0] + v[1] + v[2];
    float ss = v[0] * v[0] + v[1] * v[1] + v[2] * v[2];
    s = warpSum(s); ss = warpSum(ss);
    __shared__ float sh1[8], sh2[8];
    __shared__ float smean, srstd;
    if ((tid & 31) == 0) { sh1[tid >> 5] = s; sh2[tid >> 5] = ss; }
    __syncthreads();
    if (tid == 0) {
        float a = 0.f, b2 = 0.f;
#pragma unroll
        for (int i = 0; i < 8; i++) { a += sh1[i]; b2 += sh2[i]; }
        float m = a * (1.f / 768.f);
        smean = m;
        srstd = rsqrtf(b2 * (1.f / 768.f) - m * m + 1e-5f);
    }
    __syncthreads();
    mean = smean; rstd = srstd;
}

__global__ void ln768_h(const float* __restrict__ in,
                        const float* __restrict__ g, const float* __restrict__ be,
                        uint16_t* __restrict__ oh) {
    size_t row = blockIdx.x;
    int tid = threadIdx.x;
    float v[3], mean, rstd;
    ln_stats(in + row * EMB, tid, v, mean, rstd);
#pragma unroll
    for (int i = 0; i < 3; i++) {
        int c = tid + i * 256;
        oh[row * EMB + c] = h16((v[i] - mean) * rstd * g[c] + be[c]);
    }
}

__global__ void ln768_add(const float* __restrict__ in,
                          const float* __restrict__ g, const float* __restrict__ be,
                          float* __restrict__ out) {
    size_t row = blockIdx.x;
    int tid = threadIdx.x;
    float v[3], mean, rstd;
    ln_stats(in + row * EMB, tid, v, mean, rstd);
#pragma unroll
    for (int i = 0; i < 3; i++) {
        int c = tid + i * 256;
        out[row * EMB + c] += (v[i] - mean) * rstd * g[c] + be[c];
    }
}

__global__ void meanpool_kernel() {
    int b = blockIdx.x;
    int e = threadIdx.x;
    const float* base = g_t + (size_t)b * NTOK * EMB + e;
    float s = 0.f;
    for (int i = 0; i < NTOK; i++) s += base[(size_t)i * EMB];
    g_m[b * EMB + e] = s * (1.f / (float)NTOK);
}

// ---------------- launch -----------------------------------------------------------
extern "C" void kernel_launch(void* const* d_in, const int* in_sizes, int n_in,
                              void* d_out, int out_size) {
    const float* x    = (const float*)d_in[0];
    const float* txt  = (const float*)d_in[1];
    const float* Wpa  = (const float*)d_in[2];
    const float* bpa  = (const float*)d_in[3];
    const float* cls  = (const float*)d_in[4];
    const float* g1   = (const float*)d_in[5];
    const float* be1  = (const float*)d_in[6];
    const float* Wq   = (const float*)d_in[7];
    const float* bq   = (const float*)d_in[8];
    const float* Wk   = (const float*)d_in[9];
    const float* bk   = (const float*)d_in[10];
    const float* Wv   = (const float*)d_in[11];
    const float* bv   = (const float*)d_in[12];
    const float* Wp   = (const float*)d_in[13];
    const float* bp   = (const float*)d_in[14];
    const float* g2   = (const float*)d_in[15];
    const float* be2  = (const float*)d_in[16];
    const float* g3   = (const float*)d_in[17];
    const float* be3  = (const float*)d_in[18];
    const float* Wf   = (const float*)d_in[19];
    const float* bf   = (const float*)d_in[20];
    float* out = (float*)d_out;

    float *t, *f, *m;
    uint16_t *wh, *wl, *pah, *hh, *qh, *kh, *kl, *oh, *mh;
    cudaGetSymbolAddress((void**)&t, g_t);
    cudaGetSymbolAddress((void**)&f, g_f);
    cudaGetSymbolAddress((void**)&m, g_m);
    cudaGetSymbolAddress((void**)&wh, g_wh);
    cudaGetSymbolAddress((void**)&wl, g_wl);
    cudaGetSymbolAddress((void**)&pah, g_pa_h);
    cudaGetSymbolAddress((void**)&hh, g_h_h);
    cudaGetSymbolAddress((void**)&qh, g_q_h);
    cudaGetSymbolAddress((void**)&kh, g_k_h);
    cudaGetSymbolAddress((void**)&kl, g_k_l);
    cudaGetSymbolAddress((void**)&oh, g_o_h);
    cudaGetSymbolAddress((void**)&mh, g_m_h);

    float* v32;
    cudaGetSymbolAddress((void**)&v32, g_v);

    const int MQKV = BATCH * NTOK;    // 20928
    const int MPATCH = BATCH * NP;    // 18432
    const size_t WSZ = 768 * 768;
    dim3 tb(32, 8), wgrid(24, 24);

    // weight transpose+split, prescaled x64 (0=Wpa 1=Wq 2=Wk 3=Wv 4=Wp 5=Wf)
    wsplit_kernel<<<wgrid, tb>>>(Wpa, wh + 0 * WSZ, wl + 0 * WSZ);
    wsplit_kernel<<<wgrid, tb>>>(Wq,  wh + 1 * WSZ, wl + 1 * WSZ);
    wsplit_kernel<<<wgrid, tb>>>(Wk,  wh + 2 * WSZ, wl + 2 * WSZ);
    wsplit_kernel<<<wgrid, tb>>>(Wv,  wh + 3 * WSZ, wl + 3 * WSZ);
    wsplit_kernel<<<wgrid, tb>>>(Wp,  wh + 4 * WSZ, wl + 4 * WSZ);
    wsplit_kernel<<<wgrid, tb>>>(Wf,  wh + 5 * WSZ, wl + 5 * WSZ);

    // patches (direct fp16) + cls/text
    patch_extract_h<<<55296, 256>>>(x);
    fill_cls_text<<<7488, 256>>>(cls, txt);

    // patch GEMM -> t fp32 (remapped rows)
    gemm_h<<<dim3(12, 144), 256>>>(pah, EMB, wh + 0 * WSZ, wl + 0 * WSZ,
                                   bpa, t, nullptr, nullptr, EMB, MPATCH, 48, 1);

    // LN1 -> h fp16
    ln768_h<<<MQKV, 256>>>(t, g1, be1, hh);

    // QKV: q hi only; k hi+lo; v fp32
    dim3 gq(12, (MQKV + 127) / 128);
    gemm_h<<<gq, 256>>>(hh, EMB, wh + 1 * WSZ, wl + 1 * WSZ, bq,
                        nullptr, qh, nullptr, EMB, MQKV, 48, 0);
    gemm_h<<<gq, 256>>>(hh, EMB, wh + 2 * WSZ, wl + 2 * WSZ, bk,
                        nullptr, kh, kl, EMB, MQKV, 48, 0);
    gemm_h<<<gq, 256>>>(hh, EMB, wh + 3 * WSZ, wl + 3 * WSZ, bv,
                        v32, nullptr, nullptr, EMB, MQKV, 48, 0);

    // v transpose+split (pad k to SRS)
    vtrans_kernel<<<dim3(21, 24, BATCH), tb>>>();

    // attention
    scores_h<<<dim3(11, 6, 64), 256>>>();
    softmax_kernel<<<64 * NTOK, 256>>>();
    av_h<<<dim3(6, 6, 64), 256>>>();

    // proj -> f fp32, then t += LN2(f)
    gemm_h<<<gq, 256>>>(oh, EMB, wh + 4 * WSZ, wl + 4 * WSZ, bp,
                        f, nullptr, nullptr, EMB, MQKV, 48, 0);
    ln768_add<<<MQKV, 256>>>(f, g2, be2, t);

    // pool, LN3 -> fp16, final GEMM -> out
    meanpool_kernel<<<BATCH, 768>>>();
    ln768_h<<<BATCH, 256>>>(m, g3, be3, mh);
    gemm_h<<<dim3(12, 1), 256>>>(mh, EMB, wh + 5 * WSZ, wl + 5 * WSZ, bf,
                                 out, nullptr, nullptr, EMB, 32, 48, 0);
}